// round 1
// baseline (speedup 1.0000x reference)
#include <cuda_runtime.h>
#include <cstdint>

#define NA    57600     // 64*100*9 anchors
#define NLOC  6400      // 64*100
#define FW    100
#define PRE   6000
#define POST  300
#define NW    94        // ceil(6000/64)
#define CAP   16384
#define NBIN  65536

// Base anchors (ratios 0.5,1,2 x scales 8,16,32), precomputed incl. numpy
// banker's rounding on w/h.
__constant__ float c_base[36] = {
  -84.f,  -40.f,  99.f,  55.f,
 -176.f,  -88.f, 191.f, 103.f,
 -360.f, -184.f, 375.f, 199.f,
  -56.f,  -56.f,  71.f,  71.f,
 -120.f, -120.f, 135.f, 135.f,
 -248.f, -248.f, 263.f, 263.f,
  -36.f,  -80.f,  51.f,  95.f,
  -80.f, -168.f,  95.f, 183.f,
 -168.f, -344.f, 183.f, 359.f
};

__device__ float4             g_boxes[NA];
__device__ unsigned           g_keys[NA];
__device__ unsigned           g_hist[NBIN];
__device__ int                g_cnt;
__device__ unsigned           g_T;
__device__ unsigned long long g_cand[CAP];
__device__ float4             g_top[PRE];
__device__ unsigned long long g_mask[(size_t)PRE * NW];

// ---------------------------------------------------------------- init
__global__ void k_init() {
    int i = blockIdx.x * blockDim.x + threadIdx.x;
    int stride = gridDim.x * blockDim.x;
    for (; i < NBIN; i += stride) g_hist[i] = 0u;
    if (blockIdx.x == 0 && threadIdx.x == 0) g_cnt = 0;
}

// ---------------------------------------------------------------- decode + histogram
__global__ void k_decode(const float* __restrict__ cls,
                         const float* __restrict__ bbox,
                         const int*   __restrict__ ih,
                         const int*   __restrict__ iw) {
    int i = blockIdx.x * blockDim.x + threadIdx.x;
    if (i >= NA) return;
    int loc = i / 9, a = i % 9;
    int y = loc / FW, x = loc % FW;

    // softmax fg prob (matches jax.nn.softmax op order: max-sub, exp, div)
    float s0 = cls[(2 * a)     * NLOC + loc];
    float s1 = cls[(2 * a + 1) * NLOC + loc];
    float m  = fmaxf(s0, s1);
    float e0 = expf(s0 - m), e1 = expf(s1 - m);
    float score = e1 / (e0 + e1);

    float dx = bbox[(4 * a + 0) * NLOC + loc];
    float dy = bbox[(4 * a + 1) * NLOC + loc];
    float dw = bbox[(4 * a + 2) * NLOC + loc];
    float dh = bbox[(4 * a + 3) * NLOC + loc];

    float sx = (float)(x * 16), sy = (float)(y * 16);
    float ax1 = sx + c_base[a * 4 + 0];
    float ay1 = sy + c_base[a * 4 + 1];
    float ax2 = sx + c_base[a * 4 + 2];
    float ay2 = sy + c_base[a * 4 + 3];

    float w  = ax2 - ax1 + 1.0f;
    float h  = ay2 - ay1 + 1.0f;
    float cx = ax1 + 0.5f * w;
    float cy = ay1 + 0.5f * h;

    float pcx = dx * w + cx;
    float pcy = dy * h + cy;
    float pw  = expf(dw) * w;
    float ph  = expf(dh) * h;

    float W = (float)(iw[0] - 1);
    float H = (float)(ih[0] - 1);
    float x1 = fminf(fmaxf(pcx - 0.5f * pw, 0.f), W);
    float y1 = fminf(fmaxf(pcy - 0.5f * ph, 0.f), H);
    float x2 = fminf(fmaxf(pcx + 0.5f * pw, 0.f), W);
    float y2 = fminf(fmaxf(pcy + 0.5f * ph, 0.f), H);

    bool valid = (x2 - x1 + 1.f >= 16.f) && (y2 - y1 + 1.f >= 16.f);
    float s = valid ? score : -1e30f;

    unsigned u = __float_as_uint(s);
    unsigned key = (u & 0x80000000u) ? ~u : (u | 0x80000000u);

    g_keys[i]  = key;
    g_boxes[i] = make_float4(x1, y1, x2, y2);
    atomicAdd(&g_hist[key >> 16], 1u);
}

// ---------------------------------------------------------------- find threshold bin
__global__ void k_thresh() {
    __shared__ unsigned sh[1024];
    int t = threadIdx.x;
    int base = t * 64;
    unsigned c = 0;
    #pragma unroll 8
    for (int b = 0; b < 64; b++) c += g_hist[base + b];
    sh[t] = c;
    __syncthreads();
    // inclusive suffix sum (Hillis-Steele, reversed)
    for (int off = 1; off < 1024; off <<= 1) {
        unsigned v = (t + off < 1024) ? sh[t + off] : 0u;
        __syncthreads();
        sh[t] += v;
        __syncthreads();
    }
    unsigned suffInc = sh[t];
    unsigned above   = (t < 1023) ? sh[t + 1] : 0u;
    if (above < PRE && suffInc >= PRE) {
        unsigned run = above;
        for (int b = 63; b >= 0; b--) {
            run += g_hist[base + b];
            if (run >= PRE) { g_T = (unsigned)(base + b); break; }
        }
    }
}

// ---------------------------------------------------------------- compact candidates
__global__ void k_compact() {
    int i = blockIdx.x * blockDim.x + threadIdx.x;
    if (i >= NA) return;
    unsigned key = g_keys[i];
    if ((key >> 16) >= g_T) {
        int p = atomicAdd(&g_cnt, 1);
        if (p < CAP)
            g_cand[p] = ((unsigned long long)key << 32) | (unsigned)(~i);
    }
}

// ---------------------------------------------------------------- bitonic sort + gather
__global__ void k_sort() {
    extern __shared__ unsigned long long s[];
    int t = threadIdx.x;
    int cnt = g_cnt; if (cnt > CAP) cnt = CAP;
    for (int i = t; i < CAP; i += 1024)
        s[i] = (i < cnt) ? g_cand[i] : 0ULL;
    __syncthreads();
    for (int k = 2; k <= CAP; k <<= 1) {
        for (int j = k >> 1; j > 0; j >>= 1) {
            for (int i = t; i < CAP; i += 1024) {
                int l = i ^ j;
                if (l > i) {
                    unsigned long long a = s[i], b = s[l];
                    bool desc = ((i & k) == 0);
                    if (desc ? (a < b) : (a > b)) { s[i] = b; s[l] = a; }
                }
            }
            __syncthreads();
        }
    }
    for (int r = t; r < PRE; r += 1024) {
        unsigned idx = ~(unsigned)(s[r]);   // low 32 bits hold ~index
        if (idx < NA) g_top[r] = g_boxes[idx];
        else          g_top[r] = make_float4(0.f, 0.f, 0.f, 0.f);
    }
}

// ---------------------------------------------------------------- IoU bitmask matrix
__global__ void k_mask() {
    __shared__ float4 sb[64];
    int cb = blockIdx.x, rb = blockIdx.y, t = threadIdx.x;
    int i = rb * 64 + t;
    if (cb < rb) {                 // all j < i in this block: word is zero
        if (i < PRE) g_mask[(size_t)i * NW + cb] = 0ULL;
        return;
    }
    int j0 = cb * 64;
    int jg = j0 + t;
    sb[t] = (jg < PRE) ? g_top[jg] : make_float4(0.f, 0.f, 0.f, 0.f);
    __syncthreads();
    if (i >= PRE) return;
    float4 bi = g_top[i];
    float ai = (bi.z - bi.x) * (bi.w - bi.y);
    unsigned long long bits = 0ULL;
    #pragma unroll 4
    for (int b = 0; b < 64; b++) {
        int j = j0 + b;
        float4 bj = sb[b];
        float aj = (bj.z - bj.x) * (bj.w - bj.y);
        float lx = fmaxf(bi.x, bj.x), ly = fmaxf(bi.y, bj.y);
        float rx = fminf(bi.z, bj.z), ry = fminf(bi.w, bj.w);
        float ww = fmaxf(rx - lx, 0.f), hh = fmaxf(ry - ly, 0.f);
        float inter = ww * hh;
        float iou = inter / (ai + aj - inter);
        if (j > i && j < PRE && iou > 0.7f) bits |= 1ULL << b;
    }
    g_mask[(size_t)i * NW + cb] = bits;
}

// ---------------------------------------------------------------- sequential NMS reduce (1 warp, bit-skip)
__global__ void k_nms(float* __restrict__ out) {
    __shared__ unsigned long long rem[NW];
    __shared__ int s_keep[POST];
    __shared__ int s_next;
    int lane = threadIdx.x;
    for (int w = lane; w < NW; w += 32) rem[w] = 0ULL;
    if (lane == 0) rem[NW - 1] = ~0ULL << 48;   // block indices 6000..6015
    __syncwarp();
    int nk = 0;
    int i  = 0;
    while (nk < POST) {
        if (lane == 0) {
            int found = -1;
            int w = i >> 6;
            if (w < NW) {
                unsigned long long cur = ~rem[w] & (~0ULL << (i & 63));
                for (;;) {
                    if (cur) { found = (w << 6) + __ffsll((long long)cur) - 1; break; }
                    if (++w >= NW) break;
                    cur = ~rem[w];
                }
            }
            s_next = found;
        }
        __syncwarp();
        i = s_next;
        if (i < 0) break;
        if (lane == 0) s_keep[nk] = i;
        nk++;
        const unsigned long long* row = g_mask + (size_t)i * NW;
        for (int w = lane; w < NW; w += 32) rem[w] |= row[w];
        i++;
        __syncwarp();
    }
    for (int k = nk + lane; k < POST; k += 32) s_keep[k] = 0;
    __syncwarp();
    for (int k = lane; k < POST; k += 32) {
        float4 b = g_top[s_keep[k]];
        out[k * 5 + 0] = 0.f;
        out[k * 5 + 1] = b.x;
        out[k * 5 + 2] = b.y;
        out[k * 5 + 3] = b.z;
        out[k * 5 + 4] = b.w;
    }
}

// ---------------------------------------------------------------- launch
extern "C" void kernel_launch(void* const* d_in, const int* in_sizes, int n_in,
                              void* d_out, int out_size) {
    const float* cls  = (const float*)d_in[0];
    const float* bbox = (const float*)d_in[1];
    const int*   ih   = (const int*)d_in[2];
    const int*   iw   = (const int*)d_in[3];
    float* out = (float*)d_out;

    static bool attr_set = false;
    if (!attr_set) {
        cudaFuncSetAttribute(k_sort, cudaFuncAttributeMaxDynamicSharedMemorySize,
                             CAP * (int)sizeof(unsigned long long));
        attr_set = true;
    }

    k_init<<<64, 256>>>();
    k_decode<<<(NA + 255) / 256, 256>>>(cls, bbox, ih, iw);
    k_thresh<<<1, 1024>>>();
    k_compact<<<(NA + 255) / 256, 256>>>();
    k_sort<<<1, 1024, CAP * sizeof(unsigned long long)>>>();
    k_mask<<<dim3(NW, NW), 64>>>();
    k_nms<<<1, 32>>>(out);
}